// round 8
// baseline (speedup 1.0000x reference)
#include <cuda_runtime.h>
#include <cuda_fp16.h>
#include <cstdint>
#include <math.h>

#define BB   4
#define NQ   384
#define NK   384
#define DQI  256
#define DKI  256
#define DM   64
#define DFF  256
#define DOUT 64
#define KT   64      // k-rows per item tile
#define QG   32      // q items per group

#define SROW 528     // H / W1 row stride bytes (16B-aligned, 528 % 128 = 16 -> conflict-free)
#define SW2B 144     // W2 row stride bytes
#define W1_SLICE 8448   // 16 rows x 528 B

// ---- smem layout (one CTA, two groups) ----
#define OFF_H0  0                      // 64 x 528 = 33792
#define OFF_H1  33792                  // 64 x 528 = 33792
#define OFF_W1  67584                  // 8 slices x 8448 = 67584 (rows 0..127 of W1')
#define OFF_W2  135168                 // 256 x 144 = 36864
#define OFF_AQ0 172032                 // 1024
#define OFF_AQ1 173056                 // 1024
#define OFF_QS0 174080                 // 768
#define OFF_QS1 174848                 // 768
#define OFF_B2  175616                 // 256
#define SMEM_BYTES 175872

// ---------------- device scratch ----------------
__device__ float  g_Aq[BB * NQ * DFF];                    // fp32, exact
__device__ __align__(16) __half g_Bk[BB * NK * DFF];      // fp16
__device__ __align__(16) __half g_W1p[8 * 16 * 264];      // 8 slices [16][264] (528 B rows)
__device__ __align__(16) __half g_W2p[256 * 72];          // [256][72] (144 B rows)

// ---------------- helpers ----------------
__device__ __forceinline__ uint32_t smem_u32(const void* p) {
    uint32_t a;
    asm("{ .reg .u64 t; cvta.to.shared.u64 t, %1; cvt.u32.u64 %0, t; }" : "=r"(a) : "l"(p));
    return a;
}
__device__ __forceinline__ void ldsm4(uint32_t* r, uint32_t addr) {
    asm volatile("ldmatrix.sync.aligned.m8n8.x4.shared.b16 {%0,%1,%2,%3}, [%4];"
        : "=r"(r[0]), "=r"(r[1]), "=r"(r[2]), "=r"(r[3]) : "r"(addr));
}
__device__ __forceinline__ void ldsm4t(uint32_t* r, uint32_t addr) {
    asm volatile("ldmatrix.sync.aligned.m8n8.x4.trans.shared.b16 {%0,%1,%2,%3}, [%4];"
        : "=r"(r[0]), "=r"(r[1]), "=r"(r[2]), "=r"(r[3]) : "r"(addr));
}
__device__ __forceinline__ void mma16(float* d, const uint32_t* a, uint32_t b0, uint32_t b1) {
    asm volatile(
        "mma.sync.aligned.m16n8k16.row.col.f32.f16.f16.f32 "
        "{%0,%1,%2,%3}, {%4,%5,%6,%7}, {%8,%9}, {%0,%1,%2,%3};"
        : "+f"(d[0]), "+f"(d[1]), "+f"(d[2]), "+f"(d[3])
        : "r"(a[0]), "r"(a[1]), "r"(a[2]), "r"(a[3]), "r"(b0), "r"(b1));
}

#define CP16(d, s) asm volatile("cp.async.cg.shared.global [%0], [%1], 16;" :: "r"(d), "l"(s))
#define CPCOMMIT() asm volatile("cp.async.commit_group;")
#define CPWAIT(n)  asm volatile("cp.async.wait_group %0;" :: "n"(n))
#define BARG(id)   asm volatile("bar.sync %0, 256;" :: "r"(id) : "memory")

// ---------------- prep kernels ----------------
__global__ void prep_q(const float* __restrict__ q_inv, const float* __restrict__ Wq,
                       const float* __restrict__ bq, const float* __restrict__ W1,
                       const float* __restrict__ b1) {
    const int bqi = blockIdx.x, tid = threadIdx.x;   // 256 threads
    __shared__ float sq[DQI];
    __shared__ float sm[DM];
    sq[tid] = q_inv[(size_t)bqi * DQI + tid];
    __syncthreads();
    if (tid < DM) {
        float a0 = 0.f, a1 = 0.f, a2 = 0.f, a3 = 0.f;
        #pragma unroll 16
        for (int i = 0; i < DQI; i += 4) {
            a0 += sq[i]     * Wq[(size_t)i * DM + tid];
            a1 += sq[i + 1] * Wq[(size_t)(i + 1) * DM + tid];
            a2 += sq[i + 2] * Wq[(size_t)(i + 2) * DM + tid];
            a3 += sq[i + 3] * Wq[(size_t)(i + 3) * DM + tid];
        }
        sm[tid] = bq[tid] + ((a0 + a1) + (a2 + a3));
    }
    __syncthreads();
    float a0 = 0.f, a1 = 0.f, a2 = 0.f, a3 = 0.f;
    #pragma unroll 16
    for (int m = 0; m < DM; m += 4) {
        a0 += sm[m]     * W1[(size_t)m * DFF + tid];
        a1 += sm[m + 1] * W1[(size_t)(m + 1) * DFF + tid];
        a2 += sm[m + 2] * W1[(size_t)(m + 2) * DFF + tid];
        a3 += sm[m + 3] * W1[(size_t)(m + 3) * DFF + tid];
    }
    g_Aq[(size_t)bqi * DFF + tid] = b1[tid] + ((a0 + a1) + (a2 + a3));
}

__global__ void prep_kb(const float* __restrict__ k_inv, const float* __restrict__ Wk,
                        const float* __restrict__ bk, const float* __restrict__ W1) {
    const int bki = blockIdx.x, tid = threadIdx.x;   // 256 threads
    __shared__ float sk[DKI];
    __shared__ float sm[DM];
    sk[tid] = k_inv[(size_t)bki * DKI + tid];
    __syncthreads();
    if (tid < DM) {
        float a0 = 0.f, a1 = 0.f, a2 = 0.f, a3 = 0.f;
        #pragma unroll 16
        for (int i = 0; i < DKI; i += 4) {
            a0 += sk[i]     * Wk[(size_t)i * DM + tid];
            a1 += sk[i + 1] * Wk[(size_t)(i + 1) * DM + tid];
            a2 += sk[i + 2] * Wk[(size_t)(i + 2) * DM + tid];
            a3 += sk[i + 3] * Wk[(size_t)(i + 3) * DM + tid];
        }
        sm[tid] = bk[tid] + ((a0 + a1) + (a2 + a3));
    }
    __syncthreads();
    float a0 = 0.f, a1 = 0.f, a2 = 0.f, a3 = 0.f;
    #pragma unroll 16
    for (int m = 0; m < DM; m += 4) {
        a0 += sm[m]     * W1[(size_t)(64 + m) * DFF + tid];
        a1 += sm[m + 1] * W1[(size_t)(65 + m) * DFF + tid];
        a2 += sm[m + 2] * W1[(size_t)(66 + m) * DFF + tid];
        a3 += sm[m + 3] * W1[(size_t)(67 + m) * DFF + tid];
    }
    g_Bk[(size_t)bki * DFF + tid] = __float2half_rn((a0 + a1) + (a2 + a3));
}

// pack W1[128:256,:] -> fp16 slices [8][16][264]; W2 -> fp16 [256][72]
__global__ void prep_pack(const float* __restrict__ W1, const float* __restrict__ W2) {
    const int gid = blockIdx.x * 256 + threadIdx.x;
    if (gid < 8 * 16 * 264) {
        int s = gid / 4224, r = gid % 4224, k = r / 264, n = r % 264;
        float v = (n < 256) ? W1[(size_t)(128 + s * 16 + k) * DFF + n] : 0.f;
        g_W1p[gid] = __float2half_rn(v);
    } else {
        int h = gid - 8 * 16 * 264;
        if (h < 256 * 72) {
            int k = h / 72, n = h % 72;
            float v = (n < 64) ? W2[(size_t)k * DOUT + n] : 0.f;
            g_W2p[h] = __float2half_rn(v);
        }
    }
}

// GEMM1 K-step (W1 fully resident, no waits)
#define G1_COMPUTE(ks) do { \
    const uint32_t _slot = sb + OFF_W1 + (ks) * W1_SLICE; \
    uint32_t _a0[4], _a1[4]; \
    ldsm4(_a0, aAddr + (ks) * 32); \
    ldsm4(_a1, aAddr + 16 * SROW + (ks) * 32); \
    _Pragma("unroll") \
    for (int _p = 0; _p < 4; _p++) { \
        uint32_t _bb[4]; \
        ldsm4t(_bb, _slot + lrow * SROW + (n0 + _p * 16 + lsel * 8) * 2); \
        mma16(c1[0][2 * _p],     _a0, _bb[0], _bb[1]); \
        mma16(c1[1][2 * _p],     _a1, _bb[0], _bb[1]); \
        mma16(c1[0][2 * _p + 1], _a0, _bb[2], _bb[3]); \
        mma16(c1[1][2 * _p + 1], _a1, _bb[2], _bb[3]); \
    } \
} while (0)

// ---------------- main persistent kernel: 144 CTAs, 1/SM, 2 groups/CTA ----------------
__global__ __launch_bounds__(512, 1)
void pm_main(const float* __restrict__ q_equi, const float* __restrict__ k_equi,
             const float* __restrict__ b2, float* __restrict__ out) {
    extern __shared__ char smem[];
    const uint32_t sb = smem_u32(smem);
    const int tid = threadIdx.x;

    // ---- CTA prologue: stage W1 + W2 resident (once), b2 ----
    {
        const char* s1 = (const char*)g_W1p;
        #pragma unroll
        for (int off = 0; off < 67584; off += 8192) {
            int o = off + tid * 16;
            if (o < 67584) CP16(sb + OFF_W1 + o, s1 + o);
        }
        const char* s2 = (const char*)g_W2p;
        #pragma unroll
        for (int off = 0; off < 36864; off += 8192) {
            int o = off + tid * 16;
            if (o < 36864) CP16(sb + OFF_W2 + o, s2 + o);
        }
        CPCOMMIT();
    }
    if (tid < 64) ((float*)(smem + OFF_B2))[tid] = b2[tid];
    CPWAIT(0);
    __syncthreads();
    const float* b2s = (const float*)(smem + OFF_B2);

    // ---- group split: warps 0..7 = group 0, warps 8..15 = group 1 ----
    const int grp = tid >> 8;                 // 0 or 1
    const int gtid = tid & 255;               // tid within group
    const int w = gtid >> 5, lane = gtid & 31;
    const int g = lane >> 2, t = lane & 3;
    const int lrow = lane & 15, lsel = lane >> 4;
    const int barid = 1 + grp;

    const uint32_t offH = grp ? OFF_H1 : OFF_H0;
    char* Hb   = smem + offH;
    float* Aqs = (float*)(smem + (grp ? OFF_AQ1 : OFF_AQ0));
    float* qs  = (float*)(smem + (grp ? OFF_QS1 : OFF_QS0));

    const int kt = blockIdx.x, qs6 = blockIdx.y, b = blockIdx.z;
    const int kbase = kt * KT;
    const int qbase = qs6 * 64 + grp * QG;

    const int e = gtid & 63, kk0 = gtid >> 6;
    const float* kp0 = k_equi + (size_t)(b * NK + kbase) * 192 + e;

    const int m0 = (w >> 2) * 32, n0 = (w & 3) * 64;     // GEMM1 warp tile
    const int m2 = (w >> 1) * 16, n2 = (w & 1) * 32;     // GEMM2 warp tile
    const uint32_t aAddr  = sb + offH + (m0 + lrow) * SROW + lsel * 16;
    const uint32_t a2Addr = sb + offH + (m2 + lrow) * SROW + lsel * 16;

    for (int it = 0; it < QG; ++it) {
        const int q = qbase + it, bq = b * NQ + q;

        // ---- item prologue: stage qs/Aq (group-local) ----
        if (gtid < 192) qs[gtid] = q_equi[(size_t)bq * 192 + gtid];
        Aqs[gtid] = g_Aq[(size_t)bq * DFF + gtid];
        BARG(barid);

        // ---- build X = [dot | dist] fp16 into H rows (cols 0..127) ----
        {
            const float q0 = qs[e], q1 = qs[64 + e], q2 = qs[128 + e];
            const float qn2 = q0 * q0 + q1 * q1 + q2 * q2;
            #pragma unroll 4
            for (int j = 0; j < 16; j++) {
                int kk = kk0 + j * 4;
                const float* kp = kp0 + (size_t)kk * 192;
                float k0 = kp[0], k1 = kp[64], k2 = kp[128];
                float dot = q0 * k0 + q1 * k1 + q2 * k2;
                float kn2 = k0 * k0 + k1 * k1 + k2 * k2;
                float dist = sqrtf(fmaxf(qn2 + kn2 - 2.f * dot, 0.f));
                *(__half*)(Hb + kk * SROW + e * 2)       = __float2half_rn(dot);
                *(__half*)(Hb + kk * SROW + 128 + e * 2) = __float2half_rn(dist);
            }
        }
        BARG(barid);

        // ---- GEMM1: [64x128] @ [128x256], W1 resident, straight-line ----
        float c1[2][8][4];
        #pragma unroll
        for (int mi = 0; mi < 2; mi++)
            #pragma unroll
            for (int ni = 0; ni < 8; ni++)
                #pragma unroll
                for (int z = 0; z < 4; z++) c1[mi][ni][z] = 0.f;

        #pragma unroll
        for (int ks = 0; ks < 8; ks++) G1_COMPUTE(ks);
        BARG(barid);   // X reads done before h overwrites H

        // ---- epilogue 1: h = fp16(silu(D1 + Aq + Bk)) -> H cols 0..255 ----
        #pragma unroll
        for (int mi = 0; mi < 2; mi++) {
            const int r0 = m0 + mi * 16 + g, r1 = r0 + 8;
            const __half2* bk0 = (const __half2*)(g_Bk + (size_t)(b * NK + kbase + r0) * DFF);
            const __half2* bk1 = (const __half2*)(g_Bk + (size_t)(b * NK + kbase + r1) * DFF);
            float2 e0[8], e1[8];
            #pragma unroll
            for (int ni = 0; ni < 8; ni++) {
                int c2i = (n0 >> 1) + 4 * ni + t;
                e0[ni] = __half22float2(bk0[c2i]);
                e1[ni] = __half22float2(bk1[c2i]);
            }
            #pragma unroll
            for (int ni = 0; ni < 8; ni++) {
                int f0 = n0 + 8 * ni + 2 * t;
                float2 aq = *(const float2*)(Aqs + f0);
                float v00 = c1[mi][ni][0] + aq.x + e0[ni].x;
                float v01 = c1[mi][ni][1] + aq.y + e0[ni].y;
                float v10 = c1[mi][ni][2] + aq.x + e1[ni].x;
                float v11 = c1[mi][ni][3] + aq.y + e1[ni].y;
                v00 = v00 / (1.f + __expf(-v00));
                v01 = v01 / (1.f + __expf(-v01));
                v10 = v10 / (1.f + __expf(-v10));
                v11 = v11 / (1.f + __expf(-v11));
                *(__half2*)(Hb + r0 * SROW + f0 * 2) = __floats2half2_rn(v00, v01);
                *(__half2*)(Hb + r1 * SROW + f0 * 2) = __floats2half2_rn(v10, v11);
            }
        }
        BARG(barid);

        // ---- GEMM2: [64x256] @ [256x64], W2 resident, straight-line ----
        float c2[4][4];
        #pragma unroll
        for (int ni = 0; ni < 4; ni++)
            #pragma unroll
            for (int z = 0; z < 4; z++) c2[ni][z] = 0.f;

        #pragma unroll 4
        for (int ks = 0; ks < 16; ks++) {
            uint32_t a[4];
            ldsm4(a, a2Addr + ks * 32);
            #pragma unroll
            for (int p = 0; p < 2; p++) {
                uint32_t bb[4];
                ldsm4t(bb, sb + OFF_W2 + (ks * 16 + lrow) * SW2B + (n2 + p * 16 + lsel * 8) * 2);
                mma16(c2[2 * p],     a, bb[0], bb[1]);
                mma16(c2[2 * p + 1], a, bb[2], bb[3]);
            }
        }

        // ---- epilogue 2: + b2 -> out ----
        const size_t obase = ((size_t)bq * NK + kbase) * DOUT;
        #pragma unroll
        for (int ni = 0; ni < 4; ni++) {
            int o = n2 + 8 * ni + 2 * t;
            int r0 = m2 + g, r1 = r0 + 8;
            *(float2*)(out + obase + (size_t)r0 * DOUT + o) =
                make_float2(c2[ni][0] + b2s[o], c2[ni][1] + b2s[o + 1]);
            *(float2*)(out + obase + (size_t)r1 * DOUT + o) =
                make_float2(c2[ni][2] + b2s[o], c2[ni][3] + b2s[o + 1]);
        }
        BARG(barid);   // h reads done before next item's X build
    }
}

// ---------------- launcher ----------------
extern "C" void kernel_launch(void* const* d_in, const int* in_sizes, int n_in,
                              void* d_out, int out_size) {
    const float* q_equi = (const float*)d_in[0];
    const float* q_inv  = (const float*)d_in[1];
    const float* k_equi = (const float*)d_in[2];
    const float* k_inv  = (const float*)d_in[3];
    const float* Wq     = (const float*)d_in[4];
    const float* bq     = (const float*)d_in[5];
    const float* Wk     = (const float*)d_in[6];
    const float* bk     = (const float*)d_in[7];
    const float* W1     = (const float*)d_in[8];
    const float* b1     = (const float*)d_in[9];
    const float* W2     = (const float*)d_in[10];
    const float* b2     = (const float*)d_in[11];
    float* out = (float*)d_out;

    cudaFuncSetAttribute(pm_main, cudaFuncAttributeMaxDynamicSharedMemorySize, SMEM_BYTES);

    prep_q<<<BB * NQ, 256>>>(q_inv, Wq, bq, W1, b1);
    prep_kb<<<BB * NK, 256>>>(k_inv, Wk, bk, W1);
    prep_pack<<<(8 * 16 * 264 + 256 * 72 + 255) / 256, 256>>>(W1, W2);
    pm_main<<<dim3(NK / KT, NQ / 64, BB), 512, SMEM_BYTES>>>(q_equi, k_equi, b2, out);
}

// round 9
// speedup vs baseline: 1.3687x; 1.3687x over previous
#include <cuda_runtime.h>
#include <cuda_fp16.h>
#include <cstdint>
#include <math.h>

#define BB   4
#define NQ   384
#define NK   384
#define DQI  256
#define DKI  256
#define DM   64
#define DFF  256
#define DOUT 64
#define KT   64      // k-rows per CTA

// byte strides (16B-aligned, mod 128 = 16 -> LDSM conflict-free)
#define SROW 528     // H / W1 row stride bytes
#define SW2B 144     // W2 row stride bytes
#define W1_SLICE 8448   // 16 rows x 528 B
#define W2_CHUNK 4608   // 36864 / 8

#define OFF_H   0                      // 64 x 528 = 33792 (X cols 0..127h, h cols 0..255h)
#define OFF_W1  33792                  // 4 slots x 8448 = 33792
#define OFF_W2  67584                  // 256 x 144 = 36864
#define OFF_AQ  104448                 // 1024
#define OFF_QS  105472                 // 768
#define OFF_B2  106240                 // 256
#define SMEM_BYTES 106496

// ---------------- device scratch ----------------
__device__ float  g_Aq[BB * NQ * DFF];                    // fp32, exact
__device__ __align__(16) __half g_Bk[BB * NK * DFF];      // fp16
__device__ __align__(16) __half g_W1p[8 * 16 * 264];      // 8 slices [16][264] (528 B rows)
__device__ __align__(16) __half g_W2p[256 * 72];          // [256][72] (144 B rows)

// ---------------- helpers ----------------
__device__ __forceinline__ uint32_t smem_u32(const void* p) {
    uint32_t a;
    asm("{ .reg .u64 t; cvta.to.shared.u64 t, %1; cvt.u32.u64 %0, t; }" : "=r"(a) : "l"(p));
    return a;
}
__device__ __forceinline__ void ldsm4(uint32_t* r, uint32_t addr) {
    asm volatile("ldmatrix.sync.aligned.m8n8.x4.shared.b16 {%0,%1,%2,%3}, [%4];"
        : "=r"(r[0]), "=r"(r[1]), "=r"(r[2]), "=r"(r[3]) : "r"(addr));
}
__device__ __forceinline__ void ldsm4t(uint32_t* r, uint32_t addr) {
    asm volatile("ldmatrix.sync.aligned.m8n8.x4.trans.shared.b16 {%0,%1,%2,%3}, [%4];"
        : "=r"(r[0]), "=r"(r[1]), "=r"(r[2]), "=r"(r[3]) : "r"(addr));
}
__device__ __forceinline__ void mma16(float* d, const uint32_t* a, uint32_t b0, uint32_t b1) {
    asm volatile(
        "mma.sync.aligned.m16n8k16.row.col.f32.f16.f16.f32 "
        "{%0,%1,%2,%3}, {%4,%5,%6,%7}, {%8,%9}, {%0,%1,%2,%3};"
        : "+f"(d[0]), "+f"(d[1]), "+f"(d[2]), "+f"(d[3])
        : "r"(a[0]), "r"(a[1]), "r"(a[2]), "r"(a[3]), "r"(b0), "r"(b1));
}
// silu(v) = 0.5v + 0.5v*tanh(0.5v)   (1 MUFU + 2 FMA)
__device__ __forceinline__ float silu_f(float v) {
    float hv = 0.5f * v, th;
    asm("tanh.approx.f32 %0, %1;" : "=f"(th) : "f"(hv));
    return fmaf(hv, th, hv);
}

#define CP16(d, s) asm volatile("cp.async.cg.shared.global [%0], [%1], 16;" :: "r"(d), "l"(s))
#define CPCOMMIT() asm volatile("cp.async.commit_group;")
#define CPWAIT(n)  asm volatile("cp.async.wait_group %0;" :: "n"(n))

// ---------------- prep kernels ----------------
__global__ void prep_q(const float* __restrict__ q_inv, const float* __restrict__ Wq,
                       const float* __restrict__ bq, const float* __restrict__ W1,
                       const float* __restrict__ b1) {
    const int bqi = blockIdx.x, tid = threadIdx.x;   // 256 threads
    __shared__ float sq[DQI];
    __shared__ float sm[DM];
    sq[tid] = q_inv[(size_t)bqi * DQI + tid];
    __syncthreads();
    if (tid < DM) {
        float a0 = 0.f, a1 = 0.f, a2 = 0.f, a3 = 0.f;
        #pragma unroll 16
        for (int i = 0; i < DQI; i += 4) {
            a0 += sq[i]     * Wq[(size_t)i * DM + tid];
            a1 += sq[i + 1] * Wq[(size_t)(i + 1) * DM + tid];
            a2 += sq[i + 2] * Wq[(size_t)(i + 2) * DM + tid];
            a3 += sq[i + 3] * Wq[(size_t)(i + 3) * DM + tid];
        }
        sm[tid] = bq[tid] + ((a0 + a1) + (a2 + a3));
    }
    __syncthreads();
    float a0 = 0.f, a1 = 0.f, a2 = 0.f, a3 = 0.f;
    #pragma unroll 16
    for (int m = 0; m < DM; m += 4) {
        a0 += sm[m]     * W1[(size_t)m * DFF + tid];
        a1 += sm[m + 1] * W1[(size_t)(m + 1) * DFF + tid];
        a2 += sm[m + 2] * W1[(size_t)(m + 2) * DFF + tid];
        a3 += sm[m + 3] * W1[(size_t)(m + 3) * DFF + tid];
    }
    g_Aq[(size_t)bqi * DFF + tid] = b1[tid] + ((a0 + a1) + (a2 + a3));
}

__global__ void prep_kb(const float* __restrict__ k_inv, const float* __restrict__ Wk,
                        const float* __restrict__ bk, const float* __restrict__ W1) {
    const int bki = blockIdx.x, tid = threadIdx.x;   // 256 threads
    __shared__ float sk[DKI];
    __shared__ float sm[DM];
    sk[tid] = k_inv[(size_t)bki * DKI + tid];
    __syncthreads();
    if (tid < DM) {
        float a0 = 0.f, a1 = 0.f, a2 = 0.f, a3 = 0.f;
        #pragma unroll 16
        for (int i = 0; i < DKI; i += 4) {
            a0 += sk[i]     * Wk[(size_t)i * DM + tid];
            a1 += sk[i + 1] * Wk[(size_t)(i + 1) * DM + tid];
            a2 += sk[i + 2] * Wk[(size_t)(i + 2) * DM + tid];
            a3 += sk[i + 3] * Wk[(size_t)(i + 3) * DM + tid];
        }
        sm[tid] = bk[tid] + ((a0 + a1) + (a2 + a3));
    }
    __syncthreads();
    float a0 = 0.f, a1 = 0.f, a2 = 0.f, a3 = 0.f;
    #pragma unroll 16
    for (int m = 0; m < DM; m += 4) {
        a0 += sm[m]     * W1[(size_t)(64 + m) * DFF + tid];
        a1 += sm[m + 1] * W1[(size_t)(65 + m) * DFF + tid];
        a2 += sm[m + 2] * W1[(size_t)(66 + m) * DFF + tid];
        a3 += sm[m + 3] * W1[(size_t)(67 + m) * DFF + tid];
    }
    g_Bk[(size_t)bki * DFF + tid] = __float2half_rn((a0 + a1) + (a2 + a3));
}

// pack W1[128:256,:] -> fp16 slices [8][16][264]; W2 -> fp16 [256][72]
__global__ void prep_pack(const float* __restrict__ W1, const float* __restrict__ W2) {
    const int gid = blockIdx.x * 256 + threadIdx.x;
    if (gid < 8 * 16 * 264) {
        int s = gid / 4224, r = gid % 4224, k = r / 264, n = r % 264;
        float v = (n < 256) ? W1[(size_t)(128 + s * 16 + k) * DFF + n] : 0.f;
        g_W1p[gid] = __float2half_rn(v);
    } else {
        int h = gid - 8 * 16 * 264;
        if (h < 256 * 72) {
            int k = h / 72, n = h % 72;
            float v = (n < 64) ? W2[(size_t)k * DOUT + n] : 0.f;
            g_W2p[h] = __float2half_rn(v);
        }
    }
}

// issue W1 slice s into ring slot s&3
#define G1_ISSUE(s) do { \
    const char* _src = (const char*)g_W1p + (s) * W1_SLICE; \
    uint32_t _d = sb + OFF_W1 + ((s) & 3) * W1_SLICE + tid * 16; \
    CP16(_d, _src + tid * 16); \
    CP16(_d + 4096, _src + 4096 + tid * 16); \
    if (tid < 16) CP16(_d + 8192, _src + 8192 + tid * 16); \
} while (0)

// ---------------- main kernel: one CTA = (b, q, 64-k tile), 2 CTAs/SM ----------------
__global__ __launch_bounds__(256, 2)
void pm_main(const float* __restrict__ q_equi, const float* __restrict__ k_equi,
             const float* __restrict__ b2, float* __restrict__ out) {
    extern __shared__ char smem[];
    char* Hb = smem + OFF_H;
    float* Aqs = (float*)(smem + OFF_AQ);
    float* qs  = (float*)(smem + OFF_QS);
    float* b2s = (float*)(smem + OFF_B2);
    const uint32_t sb = smem_u32(smem);

    const int kb = blockIdx.x, q = blockIdx.y, b = blockIdx.z;
    const int kbase = kb * KT, bq = b * NQ + q;
    const int tid = threadIdx.x, w = tid >> 5, lane = tid & 31;
    const int g = lane >> 2, t = lane & 3;
    const int lrow = lane & 15, lsel = lane >> 4;

    // ---- prologue: prefetch W1 slices 0..2 (prefetch distance 3) ----
    G1_ISSUE(0); CPCOMMIT();
    G1_ISSUE(1); CPCOMMIT();
    G1_ISSUE(2); CPCOMMIT();
    if (tid < 192) qs[tid] = q_equi[(size_t)bq * 192 + tid];
    Aqs[tid] = g_Aq[(size_t)bq * DFF + tid];
    if (tid < 64) b2s[tid] = b2[tid];
    __syncthreads();

    // ---- build X = [dot | dist] (fp16), 64 rows, stride 528 B ----
    {
        const int e = tid & 63, kk0 = tid >> 6;
        const float q0 = qs[e], q1 = qs[64 + e], q2 = qs[128 + e];
        const float qn2 = q0 * q0 + q1 * q1 + q2 * q2;
        const float* kp0 = k_equi + (size_t)(b * NK + kbase) * 192 + e;
        #pragma unroll
        for (int j = 0; j < 16; j++) {
            int kk = kk0 + j * 4;
            const float* kp = kp0 + (size_t)kk * 192;
            float k0 = kp[0], k1 = kp[64], k2 = kp[128];
            float dot = q0 * k0 + q1 * k1 + q2 * k2;
            float kn2 = k0 * k0 + k1 * k1 + k2 * k2;
            float dist = sqrtf(fmaxf(qn2 + kn2 - 2.f * dot, 0.f));
            *(__half*)(Hb + kk * SROW + e * 2)       = __float2half_rn(dot);
            *(__half*)(Hb + kk * SROW + 128 + e * 2) = __float2half_rn(dist);
        }
    }
    // visibility via the __syncthreads at top of first GEMM1 iter

    // ---- GEMM1: [64x128] @ [128x256], warps 2M x 4N (32x64 tiles), 4-slot ring ----
    const int m0 = (w >> 2) * 32, n0 = (w & 3) * 64;
    float c1[2][8][4];
    #pragma unroll
    for (int mi = 0; mi < 2; mi++)
        #pragma unroll
        for (int ni = 0; ni < 8; ni++)
            #pragma unroll
            for (int z = 0; z < 4; z++) c1[mi][ni][z] = 0.f;

    const uint32_t aAddr = sb + OFF_H + (m0 + lrow) * SROW + lsel * 16;

    for (int ks = 0; ks < 8; ks++) {
        CPWAIT(2);
        __syncthreads();
        if (ks + 3 < 8) G1_ISSUE(ks + 3);
        {   // W2 chunk ks (4608 B)
            const char* src = (const char*)g_W2p + ks * W2_CHUNK;
            uint32_t d = sb + OFF_W2 + ks * W2_CHUNK + tid * 16;
            CP16(d, src + tid * 16);
            if (tid < 32) CP16(d + 4096, src + 4096 + tid * 16);
        }
        CPCOMMIT();

        const uint32_t slot = sb + OFF_W1 + (ks & 3) * W1_SLICE;
        uint32_t a[2][4];
        ldsm4(a[0], aAddr + ks * 32);
        ldsm4(a[1], aAddr + 16 * SROW + ks * 32);
        #pragma unroll
        for (int p = 0; p < 4; p++) {
            uint32_t bb[4];
            ldsm4t(bb, slot + lrow * SROW + (n0 + p * 16 + lsel * 8) * 2);
            mma16(c1[0][2 * p],     a[0], bb[0], bb[1]);
            mma16(c1[1][2 * p],     a[1], bb[0], bb[1]);
            mma16(c1[0][2 * p + 1], a[0], bb[2], bb[3]);
            mma16(c1[1][2 * p + 1], a[1], bb[2], bb[3]);
        }
    }
    CPWAIT(0);
    __syncthreads();

    // ---- epilogue 1: h = fp16(silu(D1 + Aq + Bk)) -> H (stride 528 B) ----
    #pragma unroll
    for (int mi = 0; mi < 2; mi++) {
        const int r0 = m0 + mi * 16 + g, r1 = r0 + 8;
        const __half2* bk0 = (const __half2*)(g_Bk + (size_t)(b * NK + kbase + r0) * DFF);
        const __half2* bk1 = (const __half2*)(g_Bk + (size_t)(b * NK + kbase + r1) * DFF);
        float2 e0[8], e1[8];
        #pragma unroll
        for (int ni = 0; ni < 8; ni++) {
            int c2i = (n0 >> 1) + 4 * ni + t;
            e0[ni] = __half22float2(bk0[c2i]);
            e1[ni] = __half22float2(bk1[c2i]);
        }
        #pragma unroll
        for (int ni = 0; ni < 8; ni++) {
            int f0 = n0 + 8 * ni + 2 * t;
            float2 aq = *(const float2*)(Aqs + f0);
            float v00 = silu_f(c1[mi][ni][0] + aq.x + e0[ni].x);
            float v01 = silu_f(c1[mi][ni][1] + aq.y + e0[ni].y);
            float v10 = silu_f(c1[mi][ni][2] + aq.x + e1[ni].x);
            float v11 = silu_f(c1[mi][ni][3] + aq.y + e1[ni].y);
            *(__half2*)(Hb + r0 * SROW + f0 * 2) = __floats2half2_rn(v00, v01);
            *(__half2*)(Hb + r1 * SROW + f0 * 2) = __floats2half2_rn(v10, v11);
        }
    }
    __syncthreads();

    // ---- GEMM2: [64x256] @ [256x64], warps 4M x 2N (16x32 tiles) ----
    const int m2 = (w >> 1) * 16, n2 = (w & 1) * 32;
    float c2[4][4];
    #pragma unroll
    for (int ni = 0; ni < 4; ni++)
        #pragma unroll
        for (int z = 0; z < 4; z++) c2[ni][z] = 0.f;

    const uint32_t a2Addr = sb + OFF_H + (m2 + lrow) * SROW + lsel * 16;
    #pragma unroll 4
    for (int ks = 0; ks < 16; ks++) {
        uint32_t a[4];
        ldsm4(a, a2Addr + ks * 32);
        #pragma unroll
        for (int p = 0; p < 2; p++) {
            uint32_t bb[4];
            ldsm4t(bb, sb + OFF_W2 + (ks * 16 + lrow) * SW2B + (n2 + p * 16 + lsel * 8) * 2);
            mma16(c2[2 * p],     a, bb[0], bb[1]);
            mma16(c2[2 * p + 1], a, bb[2], bb[3]);
        }
    }

    // ---- epilogue 2: + b2 -> out ----
    const size_t obase = ((size_t)bq * NK + kbase) * DOUT;
    #pragma unroll
    for (int ni = 0; ni < 4; ni++) {
        int o = n2 + 8 * ni + 2 * t;
        int r0 = m2 + g, r1 = r0 + 8;
        *(float2*)(out + obase + (size_t)r0 * DOUT + o) =
            make_float2(c2[ni][0] + b2s[o], c2[ni][1] + b2s[o + 1]);
        *(float2*)(out + obase + (size_t)r1 * DOUT + o) =
            make_float2(c2[ni][2] + b2s[o], c2[ni][3] + b2s[o + 1]);
    }
}

// ---------------- launcher ----------------
extern "C" void kernel_launch(void* const* d_in, const int* in_sizes, int n_in,
                              void* d_out, int out_size) {
    const float* q_equi = (const float*)d_in[0];
    const float* q_inv  = (const float*)d_in[1];
    const float* k_equi = (const float*)d_in[2];
    const float* k_inv  = (const float*)d_in[3];
    const float* Wq     = (const float*)d_in[4];
    const float* bq     = (const float*)d_in[5];
    const float* Wk     = (const float*)d_in[6];
    const float* bk     = (const float*)d_in[7];
    const float* W1     = (const float*)d_in[8];
    const float* b1     = (const float*)d_in[9];
    const float* W2     = (const float*)d_in[10];
    const float* b2     = (const float*)d_in[11];
    float* out = (float*)d_out;

    cudaFuncSetAttribute(pm_main, cudaFuncAttributeMaxDynamicSharedMemorySize, SMEM_BYTES);

    prep_q<<<BB * NQ, 256>>>(q_inv, Wq, bq, W1, b1);
    prep_kb<<<BB * NK, 256>>>(k_inv, Wk, bk, W1);
    prep_pack<<<(8 * 16 * 264 + 256 * 72 + 255) / 256, 256>>>(W1, W2);
    pm_main<<<dim3(NK / KT, NQ, BB), 256, SMEM_BYTES>>>(q_equi, k_equi, b2, out);
}

// round 10
// speedup vs baseline: 1.4639x; 1.0696x over previous
#include <cuda_runtime.h>
#include <cuda_fp16.h>
#include <cstdint>
#include <math.h>

#define BB   4
#define NQ   384
#define NK   384
#define DQI  256
#define DKI  256
#define DM   64
#define DFF  256
#define DOUT 64
#define KT   64      // k-rows per CTA

#define SROW 528     // H row stride bytes (16B-aligned, mod 128 = 16 -> LDSM conflict-free)

#define OFF_H   0                      // 64 x 528 = 33792 (X cols 0..127h, h cols 0..255h)
#define OFF_AQ  33792                  // 1024
#define OFF_QS  34816                  // 768
#define OFF_B2  35584                  // 256
#define SMEM_BYTES 35840

// ---------------- device scratch ----------------
__device__ float  g_Aq[BB * NQ * DFF];                    // fp32, exact
__device__ __align__(16) __half g_Bk[BB * NK * DFF];      // fp16
// per-thread mma B fragments: [ks][npair][lane] -> uint4 {b0,b1 | b0,b1}
__device__ uint4 g_W1f[8 * 16 * 32];    // 64 KB  (W1 rows 128..255, n 0..255)
__device__ uint4 g_W2f[16 * 4 * 32];    // 32 KB  (W2 k 0..255, n 0..63)

// ---------------- helpers ----------------
__device__ __forceinline__ uint32_t smem_u32(const void* p) {
    uint32_t a;
    asm("{ .reg .u64 t; cvta.to.shared.u64 t, %1; cvt.u32.u64 %0, t; }" : "=r"(a) : "l"(p));
    return a;
}
__device__ __forceinline__ void ldsm4(uint32_t* r, uint32_t addr) {
    asm volatile("ldmatrix.sync.aligned.m8n8.x4.shared.b16 {%0,%1,%2,%3}, [%4];"
        : "=r"(r[0]), "=r"(r[1]), "=r"(r[2]), "=r"(r[3]) : "r"(addr));
}
__device__ __forceinline__ void mma16(float* d, const uint32_t* a, uint32_t b0, uint32_t b1) {
    asm volatile(
        "mma.sync.aligned.m16n8k16.row.col.f32.f16.f16.f32 "
        "{%0,%1,%2,%3}, {%4,%5,%6,%7}, {%8,%9}, {%0,%1,%2,%3};"
        : "+f"(d[0]), "+f"(d[1]), "+f"(d[2]), "+f"(d[3])
        : "r"(a[0]), "r"(a[1]), "r"(a[2]), "r"(a[3]), "r"(b0), "r"(b1));
}
// silu(v) = 0.5v + 0.5v*tanh(0.5v)
__device__ __forceinline__ float silu_f(float v) {
    float hv = 0.5f * v, th;
    asm("tanh.approx.f32 %0, %1;" : "=f"(th) : "f"(hv));
    return fmaf(hv, th, hv);
}
__device__ __forceinline__ uint32_t h2u(__half2 h) { return *(uint32_t*)&h; }

// ---------------- prep kernels ----------------
__global__ void prep_q(const float* __restrict__ q_inv, const float* __restrict__ Wq,
                       const float* __restrict__ bq, const float* __restrict__ W1,
                       const float* __restrict__ b1) {
    const int bqi = blockIdx.x, tid = threadIdx.x;   // 256 threads
    __shared__ float sq[DQI];
    __shared__ float sm[DM];
    sq[tid] = q_inv[(size_t)bqi * DQI + tid];
    __syncthreads();
    if (tid < DM) {
        float a0 = 0.f, a1 = 0.f, a2 = 0.f, a3 = 0.f;
        #pragma unroll 16
        for (int i = 0; i < DQI; i += 4) {
            a0 += sq[i]     * Wq[(size_t)i * DM + tid];
            a1 += sq[i + 1] * Wq[(size_t)(i + 1) * DM + tid];
            a2 += sq[i + 2] * Wq[(size_t)(i + 2) * DM + tid];
            a3 += sq[i + 3] * Wq[(size_t)(i + 3) * DM + tid];
        }
        sm[tid] = bq[tid] + ((a0 + a1) + (a2 + a3));
    }
    __syncthreads();
    float a0 = 0.f, a1 = 0.f, a2 = 0.f, a3 = 0.f;
    #pragma unroll 16
    for (int m = 0; m < DM; m += 4) {
        a0 += sm[m]     * W1[(size_t)m * DFF + tid];
        a1 += sm[m + 1] * W1[(size_t)(m + 1) * DFF + tid];
        a2 += sm[m + 2] * W1[(size_t)(m + 2) * DFF + tid];
        a3 += sm[m + 3] * W1[(size_t)(m + 3) * DFF + tid];
    }
    g_Aq[(size_t)bqi * DFF + tid] = b1[tid] + ((a0 + a1) + (a2 + a3));
}

__global__ void prep_kb(const float* __restrict__ k_inv, const float* __restrict__ Wk,
                        const float* __restrict__ bk, const float* __restrict__ W1) {
    const int bki = blockIdx.x, tid = threadIdx.x;   // 256 threads
    __shared__ float sk[DKI];
    __shared__ float sm[DM];
    sk[tid] = k_inv[(size_t)bki * DKI + tid];
    __syncthreads();
    if (tid < DM) {
        float a0 = 0.f, a1 = 0.f, a2 = 0.f, a3 = 0.f;
        #pragma unroll 16
        for (int i = 0; i < DKI; i += 4) {
            a0 += sk[i]     * Wk[(size_t)i * DM + tid];
            a1 += sk[i + 1] * Wk[(size_t)(i + 1) * DM + tid];
            a2 += sk[i + 2] * Wk[(size_t)(i + 2) * DM + tid];
            a3 += sk[i + 3] * Wk[(size_t)(i + 3) * DM + tid];
        }
        sm[tid] = bk[tid] + ((a0 + a1) + (a2 + a3));
    }
    __syncthreads();
    float a0 = 0.f, a1 = 0.f, a2 = 0.f, a3 = 0.f;
    #pragma unroll 16
    for (int m = 0; m < DM; m += 4) {
        a0 += sm[m]     * W1[(size_t)(64 + m) * DFF + tid];
        a1 += sm[m + 1] * W1[(size_t)(65 + m) * DFF + tid];
        a2 += sm[m + 2] * W1[(size_t)(66 + m) * DFF + tid];
        a3 += sm[m + 3] * W1[(size_t)(67 + m) * DFF + tid];
    }
    g_Bk[(size_t)bki * DFF + tid] = __float2half_rn((a0 + a1) + (a2 + a3));
}

// pack W1[128:256,:] and W2 into per-thread mma B fragments
__global__ void prep_frag(const float* __restrict__ W1, const float* __restrict__ W2) {
    const int idx = blockIdx.x * 256 + threadIdx.x;
    if (idx < 8 * 16 * 32) {
        int ks = idx >> 9, npair = (idx >> 5) & 15, lane = idx & 31;
        int k0 = 128 + ks * 16 + 2 * (lane & 3);
        int na = npair * 16 + (lane >> 2), nb = na + 8;
        uint4 u;
        u.x = h2u(__floats2half2_rn(W1[(size_t)k0 * DFF + na],       W1[(size_t)(k0 + 1) * DFF + na]));
        u.y = h2u(__floats2half2_rn(W1[(size_t)(k0 + 8) * DFF + na], W1[(size_t)(k0 + 9) * DFF + na]));
        u.z = h2u(__floats2half2_rn(W1[(size_t)k0 * DFF + nb],       W1[(size_t)(k0 + 1) * DFF + nb]));
        u.w = h2u(__floats2half2_rn(W1[(size_t)(k0 + 8) * DFF + nb], W1[(size_t)(k0 + 9) * DFF + nb]));
        g_W1f[idx] = u;
    } else if (idx < 8 * 16 * 32 + 16 * 4 * 32) {
        int h = idx - 8 * 16 * 32;
        int ks = h >> 7, npair = (h >> 5) & 3, lane = h & 31;
        int k0 = ks * 16 + 2 * (lane & 3);
        int na = npair * 16 + (lane >> 2), nb = na + 8;
        uint4 u;
        u.x = h2u(__floats2half2_rn(W2[(size_t)k0 * DOUT + na],       W2[(size_t)(k0 + 1) * DOUT + na]));
        u.y = h2u(__floats2half2_rn(W2[(size_t)(k0 + 8) * DOUT + na], W2[(size_t)(k0 + 9) * DOUT + na]));
        u.z = h2u(__floats2half2_rn(W2[(size_t)k0 * DOUT + nb],       W2[(size_t)(k0 + 1) * DOUT + nb]));
        u.w = h2u(__floats2half2_rn(W2[(size_t)(k0 + 8) * DOUT + nb], W2[(size_t)(k0 + 9) * DOUT + nb]));
        g_W2f[h] = u;
    }
}

// ---------------- main kernel: one CTA = (b, q, 64-k tile), 2 CTAs/SM ----------------
__global__ __launch_bounds__(256, 2)
void pm_main(const float* __restrict__ q_equi, const float* __restrict__ k_equi,
             const float* __restrict__ b2, float* __restrict__ out) {
    extern __shared__ char smem[];
    char* Hb = smem + OFF_H;
    float* Aqs = (float*)(smem + OFF_AQ);
    float* qs  = (float*)(smem + OFF_QS);
    float* b2s = (float*)(smem + OFF_B2);
    const uint32_t sb = smem_u32(smem);

    const int kb = blockIdx.x, q = blockIdx.y, b = blockIdx.z;
    const int kbase = kb * KT, bq = b * NQ + q;
    const int tid = threadIdx.x, w = tid >> 5, lane = tid & 31;
    const int g = lane >> 2, t = lane & 3;
    const int lrow = lane & 15, lsel = lane >> 4;

    // ---- stage qs / Aq / b2 ----
    if (tid < 192) qs[tid] = q_equi[(size_t)bq * 192 + tid];
    Aqs[tid] = g_Aq[(size_t)bq * DFF + tid];
    if (tid < 64) b2s[tid] = b2[tid];
    __syncthreads();

    // ---- build X = [dot | dist] fp16 (half2 pairs), 64 rows, stride 528 B ----
    {
        const int e2 = tid & 31, kk0 = tid >> 5;   // e pair, 8 k-rows/thread
        const float2 q0 = *(const float2*)&qs[2 * e2];
        const float2 q1 = *(const float2*)&qs[64 + 2 * e2];
        const float2 q2 = *(const float2*)&qs[128 + 2 * e2];
        const float qn2x = q0.x * q0.x + q1.x * q1.x + q2.x * q2.x;
        const float qn2y = q0.y * q0.y + q1.y * q1.y + q2.y * q2.y;
        const float* kp0 = k_equi + (size_t)(b * NK + kbase) * 192 + 2 * e2;
        #pragma unroll
        for (int j = 0; j < 8; j++) {
            int kk = kk0 + j * 8;
            const float* kp = kp0 + (size_t)kk * 192;
            float2 k0 = *(const float2*)kp;
            float2 k1 = *(const float2*)(kp + 64);
            float2 k2 = *(const float2*)(kp + 128);
            float dotx = q0.x * k0.x + q1.x * k1.x + q2.x * k2.x;
            float doty = q0.y * k0.y + q1.y * k1.y + q2.y * k2.y;
            float knx = k0.x * k0.x + k1.x * k1.x + k2.x * k2.x;
            float kny = k0.y * k0.y + k1.y * k1.y + k2.y * k2.y;
            float dsx = sqrtf(fmaxf(qn2x + knx - 2.f * dotx, 0.f));
            float dsy = sqrtf(fmaxf(qn2y + kny - 2.f * doty, 0.f));
            *(__half2*)(Hb + kk * SROW + e2 * 4)       = __floats2half2_rn(dotx, doty);
            *(__half2*)(Hb + kk * SROW + 128 + e2 * 4) = __floats2half2_rn(dsx, dsy);
        }
    }
    __syncthreads();

    // ---- GEMM1: [64x128] @ [128x256], warps 2M x 4N, B from global fragments ----
    const int m0 = (w >> 2) * 32, n0 = (w & 3) * 64;
    float c1[2][8][4];
    #pragma unroll
    for (int mi = 0; mi < 2; mi++)
        #pragma unroll
        for (int ni = 0; ni < 8; ni++)
            #pragma unroll
            for (int z = 0; z < 4; z++) c1[mi][ni][z] = 0.f;

    const uint32_t aAddr = sb + OFF_H + (m0 + lrow) * SROW + lsel * 16;
    const uint4* __restrict__ w1f = g_W1f + (w & 3) * 128 + lane;

    #pragma unroll 2
    for (int ks = 0; ks < 8; ks++) {
        uint32_t a[2][4];
        ldsm4(a[0], aAddr + ks * 32);
        ldsm4(a[1], aAddr + 16 * SROW + ks * 32);
        #pragma unroll
        for (int p = 0; p < 4; p++) {
            uint4 f = w1f[ks * 512 + p * 32];
            mma16(c1[0][2 * p],     a[0], f.x, f.y);
            mma16(c1[1][2 * p],     a[1], f.x, f.y);
            mma16(c1[0][2 * p + 1], a[0], f.z, f.w);
            mma16(c1[1][2 * p + 1], a[1], f.z, f.w);
        }
    }
    __syncthreads();   // X reads done before h overwrites H

    // ---- epilogue 1: h = fp16(silu(D1 + Aq + Bk)) -> H (stride 528 B) ----
    #pragma unroll
    for (int mi = 0; mi < 2; mi++) {
        const int r0 = m0 + mi * 16 + g, r1 = r0 + 8;
        const __half2* bk0 = (const __half2*)(g_Bk + (size_t)(b * NK + kbase + r0) * DFF);
        const __half2* bk1 = (const __half2*)(g_Bk + (size_t)(b * NK + kbase + r1) * DFF);
        float2 e0[8], e1[8];
        #pragma unroll
        for (int ni = 0; ni < 8; ni++) {
            int c2i = (n0 >> 1) + 4 * ni + t;
            e0[ni] = __half22float2(bk0[c2i]);
            e1[ni] = __half22float2(bk1[c2i]);
        }
        #pragma unroll
        for (int ni = 0; ni < 8; ni++) {
            int f0 = n0 + 8 * ni + 2 * t;
            float2 aq = *(const float2*)(Aqs + f0);
            float v00 = silu_f(c1[mi][ni][0] + aq.x + e0[ni].x);
            float v01 = silu_f(c1[mi][ni][1] + aq.y + e0[ni].y);
            float v10 = silu_f(c1[mi][ni][2] + aq.x + e1[ni].x);
            float v11 = silu_f(c1[mi][ni][3] + aq.y + e1[ni].y);
            *(__half2*)(Hb + r0 * SROW + f0 * 2) = __floats2half2_rn(v00, v01);
            *(__half2*)(Hb + r1 * SROW + f0 * 2) = __floats2half2_rn(v10, v11);
        }
    }
    __syncthreads();

    // ---- GEMM2: [64x256] @ [256x64], warps 4M x 2N, B from global fragments ----
    const int m2 = (w >> 1) * 16, n2 = (w & 1) * 32;
    float c2[4][4];
    #pragma unroll
    for (int ni = 0; ni < 4; ni++)
        #pragma unroll
        for (int z = 0; z < 4; z++) c2[ni][z] = 0.f;

    const uint32_t a2Addr = sb + OFF_H + (m2 + lrow) * SROW + lsel * 16;
    const uint4* __restrict__ w2f = g_W2f + (w & 1) * 64 + lane;

    #pragma unroll 4
    for (int ks = 0; ks < 16; ks++) {
        uint32_t a[4];
        ldsm4(a, a2Addr + ks * 32);
        #pragma unroll
        for (int p = 0; p < 2; p++) {
            uint4 f = w2f[ks * 128 + p * 32];
            mma16(c2[2 * p],     a, f.x, f.y);
            mma16(c2[2 * p + 1], a, f.z, f.w);
        }
    }

    // ---- epilogue 2: + b2 -> out ----
    const size_t obase = ((size_t)bq * NK + kbase) * DOUT;
    #pragma unroll
    for (int ni = 0; ni < 4; ni++) {
        int o = n2 + 8 * ni + 2 * t;
        int r0 = m2 + g, r1 = r0 + 8;
        *(float2*)(out + obase + (size_t)r0 * DOUT + o) =
            make_float2(c2[ni][0] + b2s[o], c2[ni][1] + b2s[o + 1]);
        *(float2*)(out + obase + (size_t)r1 * DOUT + o) =
            make_float2(c2[ni][2] + b2s[o], c2[ni][3] + b2s[o + 1]);
    }
}

// ---------------- launcher ----------------
extern "C" void kernel_launch(void* const* d_in, const int* in_sizes, int n_in,
                              void* d_out, int out_size) {
    const float* q_equi = (const float*)d_in[0];
    const float* q_inv  = (const float*)d_in[1];
    const float* k_equi = (const float*)d_in[2];
    const float* k_inv  = (const float*)d_in[3];
    const float* Wq     = (const float*)d_in[4];
    const float* bq     = (const float*)d_in[5];
    const float* Wk     = (const float*)d_in[6];
    const float* bk     = (const float*)d_in[7];
    const float* W1     = (const float*)d_in[8];
    const float* b1     = (const float*)d_in[9];
    const float* W2     = (const float*)d_in[10];
    const float* b2     = (const float*)d_in[11];
    float* out = (float*)d_out;

    cudaFuncSetAttribute(pm_main, cudaFuncAttributeMaxDynamicSharedMemorySize, SMEM_BYTES);

    prep_q<<<BB * NQ, 256>>>(q_inv, Wq, bq, W1, b1);
    prep_kb<<<BB * NK, 256>>>(k_inv, Wk, bk, W1);
    prep_frag<<<(8 * 16 * 32 + 16 * 4 * 32 + 255) / 256, 256>>>(W1, W2);
    pm_main<<<dim3(NK / KT, NQ, BB), 256, SMEM_BYTES>>>(q_equi, k_equi, b2, out);
}

// round 11
// speedup vs baseline: 1.7185x; 1.1739x over previous
#include <cuda_runtime.h>
#include <cuda_fp16.h>
#include <cstdint>
#include <math.h>

#define BB   4
#define NQ   384
#define NK   384
#define DQI  256
#define DKI  256
#define DM   64
#define DFF  256
#define DOUT 64
#define KT   64      // k-rows per CTA

#define SROW 528     // H row stride bytes (16B-aligned, mod 128 = 16 -> LDSM conflict-free)

#define OFF_H   0                      // 64 x 528 = 33792 (X cols 0..127h, h cols 0..255h)
#define OFF_AQ  33792                  // 1024
#define OFF_QS  34816                  // 768
#define OFF_B2  35584                  // 256
#define SMEM_BYTES 35840

// ---------------- device scratch ----------------
__device__ float  g_Aq[BB * NQ * DFF];   // fp32, exact
// Bk packed as mma-D-fragment uint4s: [ktile16][ngroup][lane][4]
//   u0,u1 = row g (ni 0..7), u2,u3 = row g+8
__device__ uint4 g_Bkp[(BB * NK / 16) * 4 * 32 * 4];      // 768 KB
// per-thread mma B fragments: [ks][npair][lane] -> uint4 {b0,b1 | b0,b1}
__device__ uint4 g_W1f[8 * 16 * 32];    // 64 KB  (W1 rows 128..255, n 0..255)
__device__ uint4 g_W2f[16 * 4 * 32];    // 32 KB  (W2 k 0..255, n 0..63)

// ---------------- helpers ----------------
__device__ __forceinline__ uint32_t smem_u32(const void* p) {
    uint32_t a;
    asm("{ .reg .u64 t; cvta.to.shared.u64 t, %1; cvt.u32.u64 %0, t; }" : "=r"(a) : "l"(p));
    return a;
}
__device__ __forceinline__ void ldsm4(uint32_t* r, uint32_t addr) {
    asm volatile("ldmatrix.sync.aligned.m8n8.x4.shared.b16 {%0,%1,%2,%3}, [%4];"
        : "=r"(r[0]), "=r"(r[1]), "=r"(r[2]), "=r"(r[3]) : "r"(addr));
}
__device__ __forceinline__ void mma16(float* d, const uint32_t* a, uint32_t b0, uint32_t b1) {
    asm volatile(
        "mma.sync.aligned.m16n8k16.row.col.f32.f16.f16.f32 "
        "{%0,%1,%2,%3}, {%4,%5,%6,%7}, {%8,%9}, {%0,%1,%2,%3};"
        : "+f"(d[0]), "+f"(d[1]), "+f"(d[2]), "+f"(d[3])
        : "r"(a[0]), "r"(a[1]), "r"(a[2]), "r"(a[3]), "r"(b0), "r"(b1));
}
// silu(v) = 0.5v + 0.5v*tanh(0.5v)
__device__ __forceinline__ float silu_f(float v) {
    float hv = 0.5f * v, th;
    asm("tanh.approx.f32 %0, %1;" : "=f"(th) : "f"(hv));
    return fmaf(hv, th, hv);
}
__device__ __forceinline__ uint32_t h2u(__half2 h) { return *(uint32_t*)&h; }

// ---------------- merged prep kernel ----------------
// blocks [0,1536): Aq ; [1536,3072): Bk packed ; [3072,3096): weight fragments
__global__ void prep_all(const float* __restrict__ q_inv, const float* __restrict__ Wq,
                         const float* __restrict__ bq, const float* __restrict__ W1,
                         const float* __restrict__ b1,
                         const float* __restrict__ k_inv, const float* __restrict__ Wk,
                         const float* __restrict__ bk, const float* __restrict__ W2) {
    const int bx = blockIdx.x, tid = threadIdx.x;
    __shared__ float sv[DQI];
    __shared__ float sm[DM];

    if (bx < BB * NQ) {
        // ---- Aq = b1 + (q_inv@Wq + bq) @ W1[0:64,:] ----
        const int bqi = bx;
        sv[tid] = q_inv[(size_t)bqi * DQI + tid];
        __syncthreads();
        if (tid < DM) {
            float a0 = 0.f, a1 = 0.f, a2 = 0.f, a3 = 0.f;
            #pragma unroll 16
            for (int i = 0; i < DQI; i += 4) {
                a0 += sv[i]     * Wq[(size_t)i * DM + tid];
                a1 += sv[i + 1] * Wq[(size_t)(i + 1) * DM + tid];
                a2 += sv[i + 2] * Wq[(size_t)(i + 2) * DM + tid];
                a3 += sv[i + 3] * Wq[(size_t)(i + 3) * DM + tid];
            }
            sm[tid] = bq[tid] + ((a0 + a1) + (a2 + a3));
        }
        __syncthreads();
        float a0 = 0.f, a1 = 0.f, a2 = 0.f, a3 = 0.f;
        #pragma unroll 16
        for (int m = 0; m < DM; m += 4) {
            a0 += sm[m]     * W1[(size_t)m * DFF + tid];
            a1 += sm[m + 1] * W1[(size_t)(m + 1) * DFF + tid];
            a2 += sm[m + 2] * W1[(size_t)(m + 2) * DFF + tid];
            a3 += sm[m + 3] * W1[(size_t)(m + 3) * DFF + tid];
        }
        g_Aq[(size_t)bqi * DFF + tid] = b1[tid] + ((a0 + a1) + (a2 + a3));
    } else if (bx < 2 * BB * NQ) {
        // ---- Bk = (k_inv@Wk + bk) @ W1[64:128,:], packed into D-fragment layout ----
        const int bki = bx - BB * NQ;
        sv[tid] = k_inv[(size_t)bki * DKI + tid];
        __syncthreads();
        if (tid < DM) {
            float a0 = 0.f, a1 = 0.f, a2 = 0.f, a3 = 0.f;
            #pragma unroll 16
            for (int i = 0; i < DKI; i += 4) {
                a0 += sv[i]     * Wk[(size_t)i * DM + tid];
                a1 += sv[i + 1] * Wk[(size_t)(i + 1) * DM + tid];
                a2 += sv[i + 2] * Wk[(size_t)(i + 2) * DM + tid];
                a3 += sv[i + 3] * Wk[(size_t)(i + 3) * DM + tid];
            }
            sm[tid] = bk[tid] + ((a0 + a1) + (a2 + a3));
        }
        __syncthreads();
        float a0 = 0.f, a1 = 0.f, a2 = 0.f, a3 = 0.f;
        #pragma unroll 16
        for (int m = 0; m < DM; m += 4) {
            a0 += sm[m]     * W1[(size_t)(64 + m) * DFF + tid];
            a1 += sm[m + 1] * W1[(size_t)(65 + m) * DFF + tid];
            a2 += sm[m + 2] * W1[(size_t)(66 + m) * DFF + tid];
            a3 += sm[m + 3] * W1[(size_t)(67 + m) * DFF + tid];
        }
        float val = (a0 + a1) + (a2 + a3);
        // packed target: n = tid
        const int kt16 = bki >> 4, hf = (bki >> 3) & 1, g = bki & 7;
        const int lane = g * 4 + ((tid >> 1) & 3);
        const int ngroup = tid >> 6, ni = (tid & 63) >> 3;
        const int u = hf * 2 + (ni >> 2);
        size_t hidx = ((((size_t)(kt16 * 4 + ngroup) * 32 + lane) * 4 + u) * 8)
                      + (ni & 3) * 2 + (tid & 1);
        ((__half*)g_Bkp)[hidx] = __float2half_rn(val);
    } else {
        // ---- weight fragments ----
        const int idx = (bx - 2 * BB * NQ) * 256 + tid;
        if (idx < 8 * 16 * 32) {
            int ks = idx >> 9, npair = (idx >> 5) & 15, lane = idx & 31;
            int k0 = 128 + ks * 16 + 2 * (lane & 3);
            int na = npair * 16 + (lane >> 2), nb = na + 8;
            uint4 u;
            u.x = h2u(__floats2half2_rn(W1[(size_t)k0 * DFF + na],       W1[(size_t)(k0 + 1) * DFF + na]));
            u.y = h2u(__floats2half2_rn(W1[(size_t)(k0 + 8) * DFF + na], W1[(size_t)(k0 + 9) * DFF + na]));
            u.z = h2u(__floats2half2_rn(W1[(size_t)k0 * DFF + nb],       W1[(size_t)(k0 + 1) * DFF + nb]));
            u.w = h2u(__floats2half2_rn(W1[(size_t)(k0 + 8) * DFF + nb], W1[(size_t)(k0 + 9) * DFF + nb]));
            g_W1f[idx] = u;
        } else if (idx < 8 * 16 * 32 + 16 * 4 * 32) {
            int h = idx - 8 * 16 * 32;
            int ks = h >> 7, npair = (h >> 5) & 3, lane = h & 31;
            int k0 = ks * 16 + 2 * (lane & 3);
            int na = npair * 16 + (lane >> 2), nb = na + 8;
            uint4 u;
            u.x = h2u(__floats2half2_rn(W2[(size_t)k0 * DOUT + na],       W2[(size_t)(k0 + 1) * DOUT + na]));
            u.y = h2u(__floats2half2_rn(W2[(size_t)(k0 + 8) * DOUT + na], W2[(size_t)(k0 + 9) * DOUT + na]));
            u.z = h2u(__floats2half2_rn(W2[(size_t)k0 * DOUT + nb],       W2[(size_t)(k0 + 1) * DOUT + nb]));
            u.w = h2u(__floats2half2_rn(W2[(size_t)(k0 + 8) * DOUT + nb], W2[(size_t)(k0 + 9) * DOUT + nb]));
            g_W2f[h] = u;
        }
    }
}

// ---------------- main kernel: one CTA = (b, q, 64-k tile), 2 CTAs/SM ----------------
__global__ __launch_bounds__(256, 2)
void pm_main(const float* __restrict__ q_equi, const float* __restrict__ k_equi,
             const float* __restrict__ b2, float* __restrict__ out) {
    extern __shared__ char smem[];
    char* Hb = smem + OFF_H;
    float* Aqs = (float*)(smem + OFF_AQ);
    float* qs  = (float*)(smem + OFF_QS);
    float* b2s = (float*)(smem + OFF_B2);
    const uint32_t sb = smem_u32(smem);

    const int kb = blockIdx.x, q = blockIdx.y, b = blockIdx.z;
    const int kbase = kb * KT, bq = b * NQ + q;
    const int tid = threadIdx.x, w = tid >> 5, lane = tid & 31;
    const int g = lane >> 2, t = lane & 3;
    const int lrow = lane & 15, lsel = lane >> 4;

    // ---- stage qs / Aq / b2 ----
    if (tid < 192) qs[tid] = q_equi[(size_t)bq * 192 + tid];
    Aqs[tid] = g_Aq[(size_t)bq * DFF + tid];
    if (tid < 64) b2s[tid] = b2[tid];
    __syncthreads();

    // ---- build X = [dot | dist] fp16 (float4 lanes), 64 rows, stride 528 B ----
    {
        const int e4 = (tid & 15) * 4, kk0 = tid >> 4;   // 4 e's, 4 k-rows/thread
        const float4 q0 = *(const float4*)&qs[e4];
        const float4 q1 = *(const float4*)&qs[64 + e4];
        const float4 q2 = *(const float4*)&qs[128 + e4];
        const float qn0 = q0.x * q0.x + q1.x * q1.x + q2.x * q2.x;
        const float qn1 = q0.y * q0.y + q1.y * q1.y + q2.y * q2.y;
        const float qn2v = q0.z * q0.z + q1.z * q1.z + q2.z * q2.z;
        const float qn3 = q0.w * q0.w + q1.w * q1.w + q2.w * q2.w;
        const float* kp0 = k_equi + (size_t)(b * NK + kbase) * 192 + e4;
        #pragma unroll
        for (int j = 0; j < 4; j++) {
            int kk = kk0 + j * 16;
            const float* kp = kp0 + (size_t)kk * 192;
            float4 k0 = *(const float4*)kp;
            float4 k1 = *(const float4*)(kp + 64);
            float4 k2 = *(const float4*)(kp + 128);
            float d0 = q0.x * k0.x + q1.x * k1.x + q2.x * k2.x;
            float d1 = q0.y * k0.y + q1.y * k1.y + q2.y * k2.y;
            float d2 = q0.z * k0.z + q1.z * k1.z + q2.z * k2.z;
            float d3 = q0.w * k0.w + q1.w * k1.w + q2.w * k2.w;
            float n0v = k0.x * k0.x + k1.x * k1.x + k2.x * k2.x;
            float n1v = k0.y * k0.y + k1.y * k1.y + k2.y * k2.y;
            float n2v = k0.z * k0.z + k1.z * k1.z + k2.z * k2.z;
            float n3v = k0.w * k0.w + k1.w * k1.w + k2.w * k2.w;
            float s0 = sqrtf(fmaxf(qn0  + n0v - 2.f * d0, 0.f));
            float s1 = sqrtf(fmaxf(qn1  + n1v - 2.f * d1, 0.f));
            float s2 = sqrtf(fmaxf(qn2v + n2v - 2.f * d2, 0.f));
            float s3 = sqrtf(fmaxf(qn3  + n3v - 2.f * d3, 0.f));
            uint2 du, su;
            ((uint32_t*)&du)[0] = h2u(__floats2half2_rn(d0, d1));
            ((uint32_t*)&du)[1] = h2u(__floats2half2_rn(d2, d3));
            ((uint32_t*)&su)[0] = h2u(__floats2half2_rn(s0, s1));
            ((uint32_t*)&su)[1] = h2u(__floats2half2_rn(s2, s3));
            *(uint2*)(Hb + kk * SROW + e4 * 2)       = du;
            *(uint2*)(Hb + kk * SROW + 128 + e4 * 2) = su;
        }
    }
    __syncthreads();

    // ---- GEMM1: [64x128] @ [128x256], warps 2M x 4N, B from global fragments ----
    const int m0 = (w >> 2) * 32, n0 = (w & 3) * 64;
    float c1[2][8][4];
    #pragma unroll
    for (int mi = 0; mi < 2; mi++)
        #pragma unroll
        for (int ni = 0; ni < 8; ni++)
            #pragma unroll
            for (int z = 0; z < 4; z++) c1[mi][ni][z] = 0.f;

    const uint32_t aAddr = sb + OFF_H + (m0 + lrow) * SROW + lsel * 16;
    const uint4* __restrict__ w1f = g_W1f + (w & 3) * 128 + lane;

    #pragma unroll 2
    for (int ks = 0; ks < 8; ks++) {
        uint32_t a[2][4];
        ldsm4(a[0], aAddr + ks * 32);
        ldsm4(a[1], aAddr + 16 * SROW + ks * 32);
        #pragma unroll
        for (int p = 0; p < 4; p++) {
            uint4 f = w1f[ks * 512 + p * 32];
            mma16(c1[0][2 * p],     a[0], f.x, f.y);
            mma16(c1[1][2 * p],     a[1], f.x, f.y);
            mma16(c1[0][2 * p + 1], a[0], f.z, f.w);
            mma16(c1[1][2 * p + 1], a[1], f.z, f.w);
        }
    }
    __syncthreads();   // X reads done before h overwrites H

    // ---- epilogue 1: h = fp16(silu(D1 + Aq + Bk)) -> H (stride 528 B) ----
    #pragma unroll
    for (int mi = 0; mi < 2; mi++) {
        const int r0 = m0 + mi * 16 + g, r1 = r0 + 8;
        const int kt16 = (b * NK + kbase + m0 + mi * 16) >> 4;
        const uint4* __restrict__ bp = g_Bkp + ((size_t)(kt16 * 4 + (n0 >> 6)) * 32 + lane) * 4;
        __half2 he0[8], he1[8];
        ((uint4*)he0)[0] = bp[0]; ((uint4*)he0)[1] = bp[1];
        ((uint4*)he1)[0] = bp[2]; ((uint4*)he1)[1] = bp[3];
        #pragma unroll
        for (int ni = 0; ni < 8; ni++) {
            int f0 = n0 + 8 * ni + 2 * t;
            float2 aq = *(const float2*)(Aqs + f0);
            float2 e0 = __half22float2(he0[ni]);
            float2 e1 = __half22float2(he1[ni]);
            float v00 = silu_f(c1[mi][ni][0] + aq.x + e0.x);
            float v01 = silu_f(c1[mi][ni][1] + aq.y + e0.y);
            float v10 = silu_f(c1[mi][ni][2] + aq.x + e1.x);
            float v11 = silu_f(c1[mi][ni][3] + aq.y + e1.y);
            *(__half2*)(Hb + r0 * SROW + f0 * 2) = __floats2half2_rn(v00, v01);
            *(__half2*)(Hb + r1 * SROW + f0 * 2) = __floats2half2_rn(v10, v11);
        }
    }
    __syncthreads();

    // ---- GEMM2: [64x256] @ [256x64], warps 4M x 2N, B from global fragments ----
    const int m2 = (w >> 1) * 16, n2 = (w & 1) * 32;
    float c2[4][4];
    #pragma unroll
    for (int ni = 0; ni < 4; ni++)
        #pragma unroll
        for (int z = 0; z < 4; z++) c2[ni][z] = 0.f;

    const uint32_t a2Addr = sb + OFF_H + (m2 + lrow) * SROW + lsel * 16;
    const uint4* __restrict__ w2f = g_W2f + (w & 1) * 64 + lane;

    #pragma unroll 4
    for (int ks = 0; ks < 16; ks++) {
        uint32_t a[4];
        ldsm4(a, a2Addr + ks * 32);
        #pragma unroll
        for (int p = 0; p < 2; p++) {
            uint4 f = w2f[ks * 128 + p * 32];
            mma16(c2[2 * p],     a, f.x, f.y);
            mma16(c2[2 * p + 1], a, f.z, f.w);
        }
    }

    // ---- epilogue 2: + b2 -> out ----
    const size_t obase = ((size_t)bq * NK + kbase) * DOUT;
    #pragma unroll
    for (int ni = 0; ni < 4; ni++) {
        int o = n2 + 8 * ni + 2 * t;
        int r0 = m2 + g, r1 = r0 + 8;
        *(float2*)(out + obase + (size_t)r0 * DOUT + o) =
            make_float2(c2[ni][0] + b2s[o], c2[ni][1] + b2s[o + 1]);
        *(float2*)(out + obase + (size_t)r1 * DOUT + o) =
            make_float2(c2[ni][2] + b2s[o], c2[ni][3] + b2s[o + 1]);
    }
}

// ---------------- launcher ----------------
extern "C" void kernel_launch(void* const* d_in, const int* in_sizes, int n_in,
                              void* d_out, int out_size) {
    const float* q_equi = (const float*)d_in[0];
    const float* q_inv  = (const float*)d_in[1];
    const float* k_equi = (const float*)d_in[2];
    const float* k_inv  = (const float*)d_in[3];
    const float* Wq     = (const float*)d_in[4];
    const float* bq     = (const float*)d_in[5];
    const float* Wk     = (const float*)d_in[6];
    const float* bk     = (const float*)d_in[7];
    const float* W1     = (const float*)d_in[8];
    const float* b1     = (const float*)d_in[9];
    const float* W2     = (const float*)d_in[10];
    const float* b2     = (const float*)d_in[11];
    float* out = (float*)d_out;

    cudaFuncSetAttribute(pm_main, cudaFuncAttributeMaxDynamicSharedMemorySize, SMEM_BYTES);

    prep_all<<<2 * BB * NQ + 24, 256>>>(q_inv, Wq, bq, W1, b1, k_inv, Wk, bk, W2);
    pm_main<<<dim3(NK / KT, NQ, BB), 256, SMEM_BYTES>>>(q_equi, k_equi, b2, out);
}

// round 12
// speedup vs baseline: 1.8457x; 1.0740x over previous
#include <cuda_runtime.h>
#include <cuda_fp16.h>
#include <cstdint>
#include <math.h>

#define BB   4
#define NQ   384
#define NK   384
#define DQI  256
#define DKI  256
#define DM   64
#define DFF  256
#define DOUT 64
#define KT   64      // k-rows per CTA

#define SROW 528     // H row stride bytes (16B-aligned, mod 128 = 16 -> LDSM conflict-free)

#define OFF_H   0                      // 64 x 528 = 33792 (X cols 0..127h, h cols 0..255h)
#define OFF_AQ  33792                  // 1024
#define OFF_QS  34816                  // 768
#define OFF_B2  35584                  // 256
#define SMEM_BYTES 35840

// ---------------- device scratch ----------------
__device__ float  g_Aq[BB * NQ * DFF];   // fp32, exact
// Bk packed as mma-D-fragment uint4s: [ktile16][ngroup][lane][4]
//   u0,u1 = row g (ni 0..7), u2,u3 = row g+8
__device__ uint4 g_Bkp[(BB * NK / 16) * 4 * 32 * 4];      // 768 KB
// per-thread mma B fragments: [ks][npair][lane] -> uint4 {b0,b1 | b0,b1}
__device__ uint4 g_W1f[8 * 16 * 32];    // 64 KB  (W1 rows 128..255, n 0..255)
__device__ uint4 g_W2f[16 * 4 * 32];    // 32 KB  (W2 k 0..255, n 0..63)

// ---------------- helpers ----------------
__device__ __forceinline__ uint32_t smem_u32(const void* p) {
    uint32_t a;
    asm("{ .reg .u64 t; cvta.to.shared.u64 t, %1; cvt.u32.u64 %0, t; }" : "=r"(a) : "l"(p));
    return a;
}
__device__ __forceinline__ void ldsm4(uint32_t* r, uint32_t addr) {
    asm volatile("ldmatrix.sync.aligned.m8n8.x4.shared.b16 {%0,%1,%2,%3}, [%4];"
        : "=r"(r[0]), "=r"(r[1]), "=r"(r[2]), "=r"(r[3]) : "r"(addr));
}
__device__ __forceinline__ void mma16(float* d, const uint32_t* a, uint32_t b0, uint32_t b1) {
    asm volatile(
        "mma.sync.aligned.m16n8k16.row.col.f32.f16.f16.f32 "
        "{%0,%1,%2,%3}, {%4,%5,%6,%7}, {%8,%9}, {%0,%1,%2,%3};"
        : "+f"(d[0]), "+f"(d[1]), "+f"(d[2]), "+f"(d[3])
        : "r"(a[0]), "r"(a[1]), "r"(a[2]), "r"(a[3]), "r"(b0), "r"(b1));
}
// silu(v) = 0.5v + 0.5v*tanh(0.5v)
__device__ __forceinline__ float silu_f(float v) {
    float hv = 0.5f * v, th;
    asm("tanh.approx.f32 %0, %1;" : "=f"(th) : "f"(hv));
    return fmaf(hv, th, hv);
}
__device__ __forceinline__ uint32_t h2u(__half2 h) { return *(uint32_t*)&h; }

// ---------------- merged prep kernel ----------------
// blocks [0,1536): Aq ; [1536,3072): Bk packed ; [3072,3096): weight fragments
__global__ void prep_all(const float* __restrict__ q_inv, const float* __restrict__ Wq,
                         const float* __restrict__ bq, const float* __restrict__ W1,
                         const float* __restrict__ b1,
                         const float* __restrict__ k_inv, const float* __restrict__ Wk,
                         const float* __restrict__ bk, const float* __restrict__ W2) {
    const int bx = blockIdx.x, tid = threadIdx.x;
    __shared__ float sv[DQI];
    __shared__ float sm[DM];

    if (bx < BB * NQ) {
        const int bqi = bx;
        sv[tid] = q_inv[(size_t)bqi * DQI + tid];
        __syncthreads();
        if (tid < DM) {
            float a0 = 0.f, a1 = 0.f, a2 = 0.f, a3 = 0.f;
            #pragma unroll 16
            for (int i = 0; i < DQI; i += 4) {
                a0 += sv[i]     * Wq[(size_t)i * DM + tid];
                a1 += sv[i + 1] * Wq[(size_t)(i + 1) * DM + tid];
                a2 += sv[i + 2] * Wq[(size_t)(i + 2) * DM + tid];
                a3 += sv[i + 3] * Wq[(size_t)(i + 3) * DM + tid];
            }
            sm[tid] = bq[tid] + ((a0 + a1) + (a2 + a3));
        }
        __syncthreads();
        float a0 = 0.f, a1 = 0.f, a2 = 0.f, a3 = 0.f;
        #pragma unroll 16
        for (int m = 0; m < DM; m += 4) {
            a0 += sm[m]     * W1[(size_t)m * DFF + tid];
            a1 += sm[m + 1] * W1[(size_t)(m + 1) * DFF + tid];
            a2 += sm[m + 2] * W1[(size_t)(m + 2) * DFF + tid];
            a3 += sm[m + 3] * W1[(size_t)(m + 3) * DFF + tid];
        }
        g_Aq[(size_t)bqi * DFF + tid] = b1[tid] + ((a0 + a1) + (a2 + a3));
    } else if (bx < 2 * BB * NQ) {
        const int bki = bx - BB * NQ;
        sv[tid] = k_inv[(size_t)bki * DKI + tid];
        __syncthreads();
        if (tid < DM) {
            float a0 = 0.f, a1 = 0.f, a2 = 0.f, a3 = 0.f;
            #pragma unroll 16
            for (int i = 0; i < DKI; i += 4) {
                a0 += sv[i]     * Wk[(size_t)i * DM + tid];
                a1 += sv[i + 1] * Wk[(size_t)(i + 1) * DM + tid];
                a2 += sv[i + 2] * Wk[(size_t)(i + 2) * DM + tid];
                a3 += sv[i + 3] * Wk[(size_t)(i + 3) * DM + tid];
            }
            sm[tid] = bk[tid] + ((a0 + a1) + (a2 + a3));
        }
        __syncthreads();
        float a0 = 0.f, a1 = 0.f, a2 = 0.f, a3 = 0.f;
        #pragma unroll 16
        for (int m = 0; m < DM; m += 4) {
            a0 += sm[m]     * W1[(size_t)(64 + m) * DFF + tid];
            a1 += sm[m + 1] * W1[(size_t)(65 + m) * DFF + tid];
            a2 += sm[m + 2] * W1[(size_t)(66 + m) * DFF + tid];
            a3 += sm[m + 3] * W1[(size_t)(67 + m) * DFF + tid];
        }
        float val = (a0 + a1) + (a2 + a3);
        const int kt16 = bki >> 4, hf = (bki >> 3) & 1, g = bki & 7;
        const int lane = g * 4 + ((tid >> 1) & 3);
        const int ngroup = tid >> 6, ni = (tid & 63) >> 3;
        const int u = hf * 2 + (ni >> 2);
        size_t hidx = ((((size_t)(kt16 * 4 + ngroup) * 32 + lane) * 4 + u) * 8)
                      + (ni & 3) * 2 + (tid & 1);
        ((__half*)g_Bkp)[hidx] = __float2half_rn(val);
    } else {
        const int idx = (bx - 2 * BB * NQ) * 256 + tid;
        if (idx < 8 * 16 * 32) {
            int ks = idx >> 9, npair = (idx >> 5) & 15, lane = idx & 31;
            int k0 = 128 + ks * 16 + 2 * (lane & 3);
            int na = npair * 16 + (lane >> 2), nb = na + 8;
            uint4 u;
            u.x = h2u(__floats2half2_rn(W1[(size_t)k0 * DFF + na],       W1[(size_t)(k0 + 1) * DFF + na]));
            u.y = h2u(__floats2half2_rn(W1[(size_t)(k0 + 8) * DFF + na], W1[(size_t)(k0 + 9) * DFF + na]));
            u.z = h2u(__floats2half2_rn(W1[(size_t)k0 * DFF + nb],       W1[(size_t)(k0 + 1) * DFF + nb]));
            u.w = h2u(__floats2half2_rn(W1[(size_t)(k0 + 8) * DFF + nb], W1[(size_t)(k0 + 9) * DFF + nb]));
            g_W1f[idx] = u;
        } else if (idx < 8 * 16 * 32 + 16 * 4 * 32) {
            int h = idx - 8 * 16 * 32;
            int ks = h >> 7, npair = (h >> 5) & 3, lane = h & 31;
            int k0 = ks * 16 + 2 * (lane & 3);
            int na = npair * 16 + (lane >> 2), nb = na + 8;
            uint4 u;
            u.x = h2u(__floats2half2_rn(W2[(size_t)k0 * DOUT + na],       W2[(size_t)(k0 + 1) * DOUT + na]));
            u.y = h2u(__floats2half2_rn(W2[(size_t)(k0 + 8) * DOUT + na], W2[(size_t)(k0 + 9) * DOUT + na]));
            u.z = h2u(__floats2half2_rn(W2[(size_t)k0 * DOUT + nb],       W2[(size_t)(k0 + 1) * DOUT + nb]));
            u.w = h2u(__floats2half2_rn(W2[(size_t)(k0 + 8) * DOUT + nb], W2[(size_t)(k0 + 9) * DOUT + nb]));
            g_W2f[h] = u;
        }
    }
}

// ---------------- main kernel: one CTA = (b, q, 64-k tile), 3 CTAs/SM ----------------
__global__ __launch_bounds__(256, 3)
void pm_main(const float* __restrict__ q_equi, const float* __restrict__ k_equi,
             const float* __restrict__ b2, float* __restrict__ out) {
    extern __shared__ char smem[];
    char* Hb = smem + OFF_H;
    float* Aqs = (float*)(smem + OFF_AQ);
    float* qs  = (float*)(smem + OFF_QS);
    float* b2s = (float*)(smem + OFF_B2);
    const uint32_t sb = smem_u32(smem);

    const int kb = blockIdx.x, q = blockIdx.y, b = blockIdx.z;
    const int kbase = kb * KT, bq = b * NQ + q;
    const int tid = threadIdx.x, w = tid >> 5, lane = tid & 31;
    const int g = lane >> 2, t = lane & 3;
    const int lrow = lane & 15, lsel = lane >> 4;

    // ---- stage qs / Aq / b2 ----
    if (tid < 192) qs[tid] = q_equi[(size_t)bq * 192 + tid];
    Aqs[tid] = g_Aq[(size_t)bq * DFF + tid];
    if (tid < 64) b2s[tid] = b2[tid];
    __syncthreads();

    // ---- build X = [dot | dist] fp16 (float4 lanes), 64 rows, stride 528 B ----
    {
        const int e4 = (tid & 15) * 4, kk0 = tid >> 4;
        const float4 q0 = *(const float4*)&qs[e4];
        const float4 q1 = *(const float4*)&qs[64 + e4];
        const float4 q2 = *(const float4*)&qs[128 + e4];
        const float qn0 = q0.x * q0.x + q1.x * q1.x + q2.x * q2.x;
        const float qn1 = q0.y * q0.y + q1.y * q1.y + q2.y * q2.y;
        const float qn2v = q0.z * q0.z + q1.z * q1.z + q2.z * q2.z;
        const float qn3 = q0.w * q0.w + q1.w * q1.w + q2.w * q2.w;
        const float* kp0 = k_equi + (size_t)(b * NK + kbase) * 192 + e4;
        #pragma unroll
        for (int j = 0; j < 4; j++) {
            int kk = kk0 + j * 16;
            const float* kp = kp0 + (size_t)kk * 192;
            float4 k0 = *(const float4*)kp;
            float4 k1 = *(const float4*)(kp + 64);
            float4 k2 = *(const float4*)(kp + 128);
            float d0 = q0.x * k0.x + q1.x * k1.x + q2.x * k2.x;
            float d1 = q0.y * k0.y + q1.y * k1.y + q2.y * k2.y;
            float d2 = q0.z * k0.z + q1.z * k1.z + q2.z * k2.z;
            float d3 = q0.w * k0.w + q1.w * k1.w + q2.w * k2.w;
            float n0v = k0.x * k0.x + k1.x * k1.x + k2.x * k2.x;
            float n1v = k0.y * k0.y + k1.y * k1.y + k2.y * k2.y;
            float n2v = k0.z * k0.z + k1.z * k1.z + k2.z * k2.z;
            float n3v = k0.w * k0.w + k1.w * k1.w + k2.w * k2.w;
            float s0 = sqrtf(fmaxf(qn0  + n0v - 2.f * d0, 0.f));
            float s1 = sqrtf(fmaxf(qn1  + n1v - 2.f * d1, 0.f));
            float s2 = sqrtf(fmaxf(qn2v + n2v - 2.f * d2, 0.f));
            float s3 = sqrtf(fmaxf(qn3  + n3v - 2.f * d3, 0.f));
            uint2 du, su;
            ((uint32_t*)&du)[0] = h2u(__floats2half2_rn(d0, d1));
            ((uint32_t*)&du)[1] = h2u(__floats2half2_rn(d2, d3));
            ((uint32_t*)&su)[0] = h2u(__floats2half2_rn(s0, s1));
            ((uint32_t*)&su)[1] = h2u(__floats2half2_rn(s2, s3));
            *(uint2*)(Hb + kk * SROW + e4 * 2)       = du;
            *(uint2*)(Hb + kk * SROW + 128 + e4 * 2) = su;
        }
    }
    __syncthreads();

    // ---- GEMM1 in two N-phases (32-reg accumulators), warps 2M x 4N of 32x32 ----
    const int m0 = (w >> 2) * 32, nw = (w & 3) * 32;
    const uint32_t aAddr = sb + OFF_H + (m0 + lrow) * SROW + lsel * 16;
    const int kt16a = (b * NK + kbase + m0) >> 4;       // ktile16 for mi=0
    const int half = (nw >> 5) & 1;                      // which half of 64-group

    #pragma unroll
    for (int ph = 1; ph >= 0; ph--) {                    // ph=1: cols 128..255 ; ph=0: cols 0..127
        const int nbase = ph * 128 + nw;
        float c1[2][4][4];
        #pragma unroll
        for (int mi = 0; mi < 2; mi++)
            #pragma unroll
            for (int ni = 0; ni < 4; ni++)
                #pragma unroll
                for (int z = 0; z < 4; z++) c1[mi][ni][z] = 0.f;

        const uint4* __restrict__ w1f = g_W1f + (nbase >> 4) * 32 + lane;
        #pragma unroll 2
        for (int ks = 0; ks < 8; ks++) {
            uint32_t a[2][4];
            ldsm4(a[0], aAddr + ks * 32);
            ldsm4(a[1], aAddr + 16 * SROW + ks * 32);
            #pragma unroll
            for (int p = 0; p < 2; p++) {
                uint4 f = w1f[ks * 512 + p * 32];
                mma16(c1[0][2 * p],     a[0], f.x, f.y);
                mma16(c1[1][2 * p],     a[1], f.x, f.y);
                mma16(c1[0][2 * p + 1], a[0], f.z, f.w);
                mma16(c1[1][2 * p + 1], a[1], f.z, f.w);
            }
        }

        if (ph == 0) __syncthreads();    // phase-B epilogue overwrites X: wait for all X reads

        // ---- epilogue: h = fp16(silu(D1 + Aq + Bk)) for this 128-col phase ----
        #pragma unroll
        for (int mi = 0; mi < 2; mi++) {
            const int r0 = m0 + mi * 16 + g, r1 = r0 + 8;
            const uint4* __restrict__ bp =
                g_Bkp + ((size_t)((kt16a + mi) * 4 + (nbase >> 6)) * 32 + lane) * 4;
            uint4 u0 = bp[half], u1 = bp[2 + half];
            const __half2* he0 = (const __half2*)&u0;
            const __half2* he1 = (const __half2*)&u1;
            #pragma unroll
            for (int ni = 0; ni < 4; ni++) {
                int f0 = nbase + 8 * ni + 2 * t;
                float2 aq = *(const float2*)(Aqs + f0);
                float2 e0 = __half22float2(he0[ni]);
                float2 e1 = __half22float2(he1[ni]);
                float v00 = silu_f(c1[mi][ni][0] + aq.x + e0.x);
                float v01 = silu_f(c1[mi][ni][1] + aq.y + e0.y);
                float v10 = silu_f(c1[mi][ni][2] + aq.x + e1.x);
                float v11 = silu_f(c1[mi][ni][3] + aq.y + e1.y);
                *(__half2*)(Hb + r0 * SROW + f0 * 2) = __floats2half2_rn(v00, v01);
                *(__half2*)(Hb + r1 * SROW + f0 * 2) = __floats2half2_rn(v10, v11);
            }
        }
    }
    __syncthreads();

    // ---- GEMM2: [64x256] @ [256x64], warps 4M x 2N, B from global fragments ----
    const int m2 = (w >> 1) * 16, n2 = (w & 1) * 32;
    float c2[4][4];
    #pragma unroll
    for (int ni = 0; ni < 4; ni++)
        #pragma unroll
        for (int z = 0; z < 4; z++) c2[ni][z] = 0.f;

    const uint32_t a2Addr = sb + OFF_H + (m2 + lrow) * SROW + lsel * 16;
    const uint4* __restrict__ w2f = g_W2f + (w & 1) * 64 + lane;

    #pragma unroll 4
    for (int ks = 0; ks < 16; ks++) {
        uint32_t a[4];
        ldsm4(a, a2Addr + ks * 32);
        #pragma unroll
        for (int p = 0; p < 2; p++) {
            uint4 f = w2f[ks * 128 + p * 32];
            mma16(c2[2 * p],     a, f.x, f.y);
            mma16(c2[2 * p + 1], a, f.z, f.w);
        }
    }

    // ---- epilogue 2: + b2 -> out ----
    const size_t obase = ((size_t)bq * NK + kbase) * DOUT;
    #pragma unroll
    for (int ni = 0; ni < 4; ni++) {
        int o = n2 + 8 * ni + 2 * t;
        int r0 = m2 + g, r1 = r0 + 8;
        *(float2*)(out + obase + (size_t)r0 * DOUT + o) =
            make_float2(c2[ni][0] + b2s[o], c2[ni][1] + b2s[o + 1]);
        *(float2*)(out + obase + (size_t)r1 * DOUT + o) =
            make_float2(c2[ni][2] + b2s[o], c2[ni][3] + b2s[o + 1]);
    }
}

// ---------------- launcher ----------------
extern "C" void kernel_launch(void* const* d_in, const int* in_sizes, int n_in,
                              void* d_out, int out_size) {
    const float* q_equi = (const float*)d_in[0];
    const float* q_inv  = (const float*)d_in[1];
    const float* k_equi = (const float*)d_in[2];
    const float* k_inv  = (const float*)d_in[3];
    const float* Wq     = (const float*)d_in[4];
    const float* bq     = (const float*)d_in[5];
    const float* Wk     = (const float*)d_in[6];
    const float* bk     = (const float*)d_in[7];
    const float* W1     = (const float*)d_in[8];
    const float* b1     = (const float*)d_in[9];
    const float* W2     = (const float*)d_in[10];
    const float* b2     = (const float*)d_in[11];
    float* out = (float*)d_out;

    cudaFuncSetAttribute(pm_main, cudaFuncAttributeMaxDynamicSharedMemorySize, SMEM_BYTES);

    prep_all<<<2 * BB * NQ + 24, 256>>>(q_inv, Wq, bq, W1, b1, k_inv, Wk, bk, W2);
    pm_main<<<dim3(NK / KT, NQ, BB), 256, SMEM_BYTES>>>(q_equi, k_equi, b2, out);
}